// round 1
// baseline (speedup 1.0000x reference)
#include <cuda_runtime.h>

#define IH 384
#define IW 384
#define HO 382
#define WO 382
#define NB 8
#define NC 3

__global__ __launch_bounds__(256, 3)
void deform_fused_kernel(const float* __restrict__ x,
                         const float* __restrict__ w1,
                         const float* __restrict__ b1,
                         const float* __restrict__ w2,
                         const float* __restrict__ b2,
                         float* __restrict__ out)
{
    __shared__ float s_w1[18 * 27];
    __shared__ float s_b1[18];
    __shared__ float s_w2[3 * 27];
    __shared__ float s_b2[3];

    int tid = threadIdx.y * blockDim.x + threadIdx.x;
    for (int i = tid; i < 18 * 27; i += 256) s_w1[i] = w1[i];
    for (int i = tid; i < 3 * 27;  i += 256) s_w2[i] = w2[i];
    if (tid < 18) s_b1[tid] = b1[tid];
    if (tid < 3)  s_b2[tid] = b2[tid];
    __syncthreads();

    int wo = blockIdx.x * 32 + threadIdx.x;
    int ho = blockIdx.y * 8  + threadIdx.y;
    int b  = blockIdx.z;
    if (wo >= WO || ho >= HO) return;

    const float* __restrict__ xb = x + (size_t)b * NC * IH * IW;

    // Load the 3x3x3 input window (shared by offset-conv)
    float win[27];
#pragma unroll
    for (int ci = 0; ci < 3; ci++)
#pragma unroll
        for (int kh = 0; kh < 3; kh++)
#pragma unroll
            for (int kw = 0; kw < 3; kw++)
                win[ci * 9 + kh * 3 + kw] =
                    __ldg(xb + ((size_t)ci * IH + (ho + kh)) * IW + (wo + kw));

    float acc0 = s_b2[0];
    float acc1 = s_b2[1];
    float acc2 = s_b2[2];

#pragma unroll
    for (int kk = 0; kk < 9; kk++) {
        // offset channels: 2*kk = dy, 2*kk+1 = dx
        float dy = s_b1[2 * kk];
        float dx = s_b1[2 * kk + 1];
        const float* __restrict__ wdy = &s_w1[(2 * kk)     * 27];
        const float* __restrict__ wdx = &s_w1[(2 * kk + 1) * 27];
#pragma unroll
        for (int j = 0; j < 27; j++) {
            dy = fmaf(win[j], wdy[j], dy);
            dx = fmaf(win[j], wdx[j], dx);
        }

        int kh = kk / 3;
        int kw = kk % 3;
        float py = (float)(ho + kh) + dy;
        float px = (float)(wo + kw) + dx;
        float fy0 = floorf(py);
        float fx0 = floorf(px);
        float wy = py - fy0;
        float wx = px - fx0;
        int y0 = (int)fy0;
        int x0 = (int)fx0;

        bool vy0 = (y0 >= 0)     && (y0 <= IH - 1);
        bool vy1 = (y0 >= -1)    && (y0 <= IH - 2);
        bool vx0 = (x0 >= 0)     && (x0 <= IW - 1);
        bool vx1 = (x0 >= -1)    && (x0 <= IW - 2);

        int yc0 = min(max(y0,     0), IH - 1);
        int yc1 = min(max(y0 + 1, 0), IH - 1);
        int xc0 = min(max(x0,     0), IW - 1);
        int xc1 = min(max(x0 + 1, 0), IW - 1);

        float m00 = (1.f - wy) * (1.f - wx) * ((vy0 && vx0) ? 1.f : 0.f);
        float m01 = (1.f - wy) * wx         * ((vy0 && vx1) ? 1.f : 0.f);
        float m10 = wy         * (1.f - wx) * ((vy1 && vx0) ? 1.f : 0.f);
        float m11 = wy         * wx         * ((vy1 && vx1) ? 1.f : 0.f);

        int i00 = yc0 * IW + xc0;
        int i01 = yc0 * IW + xc1;
        int i10 = yc1 * IW + xc0;
        int i11 = yc1 * IW + xc1;

#pragma unroll
        for (int c = 0; c < 3; c++) {
            const float* __restrict__ xc = xb + (size_t)c * IH * IW;
            float v = m00 * __ldg(xc + i00)
                    + m01 * __ldg(xc + i01)
                    + m10 * __ldg(xc + i10)
                    + m11 * __ldg(xc + i11);
            acc0 = fmaf(v, s_w2[0 * 27 + c * 9 + kk], acc0);
            acc1 = fmaf(v, s_w2[1 * 27 + c * 9 + kk], acc1);
            acc2 = fmaf(v, s_w2[2 * 27 + c * 9 + kk], acc2);
        }
    }

    size_t obase = ((size_t)b * NC) * (size_t)(HO * WO) + (size_t)ho * WO + wo;
    out[obase]               = acc0;
    out[obase + HO * WO]     = acc1;
    out[obase + 2 * HO * WO] = acc2;
}

extern "C" void kernel_launch(void* const* d_in, const int* in_sizes, int n_in,
                              void* d_out, int out_size)
{
    const float* x  = (const float*)d_in[0];
    const float* w1 = (const float*)d_in[1];
    const float* b1 = (const float*)d_in[2];
    const float* w2 = (const float*)d_in[3];
    const float* b2 = (const float*)d_in[4];
    float* out = (float*)d_out;

    dim3 block(32, 8, 1);
    dim3 grid((WO + 31) / 32, (HO + 7) / 8, NB);
    deform_fused_kernel<<<grid, block>>>(x, w1, b1, w2, b2, out);
}

// round 2
// speedup vs baseline: 1.1058x; 1.1058x over previous
#include <cuda_runtime.h>

#define IH 384
#define IW 384
#define HO 382
#define WO 382
#define NB 8
#define HALO 6
#define TH 22          // 8 + 3 + 2*HALO - 1  rows covered: [ho0-6, ho0+15]
#define TW 46          // 32 + 2 + 2*HALO     cols covered: [wo0-6, wo0+39]
#define TILE_CH (TH * TW)   // 1012

typedef unsigned long long u64;

__device__ __forceinline__ u64 fma2(u64 a, u64 b, u64 c) {
    u64 d;
    asm("fma.rn.f32x2 %0, %1, %2, %3;" : "=l"(d) : "l"(a), "l"(b), "l"(c));
    return d;
}
__device__ __forceinline__ u64 pack2(float lo, float hi) {
    u64 r;
    asm("mov.b64 %0, {%1, %2};" : "=l"(r) : "f"(lo), "f"(hi));
    return r;
}
__device__ __forceinline__ void unpack2(u64 v, float& lo, float& hi) {
    asm("mov.b64 {%0, %1}, %2;" : "=f"(lo), "=f"(hi) : "l"(v));
}

__global__ __launch_bounds__(128, 4)
void deform_fused2(const float* __restrict__ x,
                   const float* __restrict__ w1,
                   const float* __restrict__ b1,
                   const float* __restrict__ w2,
                   const float* __restrict__ b2,
                   float* __restrict__ out)
{
    __shared__ float s_tile[3 * TILE_CH];
    __shared__ __align__(16) u64 s_w1p[9 * 28];   // [kk][j] packed (wdy, wdx), stride 28 keeps 16B align
    __shared__ u64 s_b1p[9];
    __shared__ float s_w2[3 * 27];
    __shared__ float s_b2[3];

    const int tid = threadIdx.y * 32 + threadIdx.x;

    // ---- weights to shared ----
    for (int i = tid; i < 9 * 27; i += 128) {
        int kk = i / 27, j = i % 27;
        s_w1p[kk * 28 + j] = pack2(w1[(2 * kk) * 27 + j], w1[(2 * kk + 1) * 27 + j]);
    }
    for (int i = tid; i < 9; i += 128) {
        s_w1p[i * 28 + 27] = 0ull;                 // pad slot
        s_b1p[i] = pack2(b1[2 * i], b1[2 * i + 1]);
    }
    if (tid < 81) s_w2[tid] = w2[tid];
    if (tid < 3)  s_b2[tid] = b2[tid];

    const int wo0 = blockIdx.x * 32;
    const int ho0 = blockIdx.y * 8;
    const int b   = blockIdx.z;
    const float* __restrict__ xb = x + (size_t)b * 3 * IH * IW;

    const int rowBase = ho0 - HALO;
    const int colBase = wo0 - HALO;

    // ---- input tile to shared (zero-filled outside image) ----
    for (int i = tid; i < 3 * TILE_CH; i += 128) {
        int c  = i / TILE_CH;
        int rr = i - c * TILE_CH;
        int r  = rr / TW;
        int col = rr - r * TW;
        int gy = rowBase + r;
        int gx = colBase + col;
        float v = 0.f;
        if ((unsigned)gy < IH && (unsigned)gx < IW)
            v = __ldg(xb + ((size_t)c * IH + gy) * IW + gx);
        s_tile[i] = v;
    }
    __syncthreads();

    const int wo  = wo0 + threadIdx.x;       // may be >= WO for 2 lanes in edge blocks
    const int hoA = ho0 + 2 * threadIdx.y;   // pixel pair rows hoA, hoA+1
    const int ltx = threadIdx.x + HALO;
    const int lty = 2 * threadIdx.y + HALO;

    // ---- window (4 rows x 3 cols x 3 ch) duplicated-packed in registers ----
    u64 wr2[3][4][3];
#pragma unroll
    for (int c = 0; c < 3; c++)
#pragma unroll
        for (int r = 0; r < 4; r++)
#pragma unroll
            for (int kw = 0; kw < 3; kw++) {
                float v = s_tile[c * TILE_CH + (lty + r) * TW + (ltx + kw)];
                wr2[c][r][kw] = pack2(v, v);
            }

    float acc[2][3];
#pragma unroll
    for (int p = 0; p < 2; p++)
#pragma unroll
        for (int o = 0; o < 3; o++) acc[p][o] = s_b2[o];

#pragma unroll 1
    for (int kk = 0; kk < 9; kk++) {
        // ---- offset conv for this kk, both pixels, packed (dy,dx) ----
        u64 a0 = s_b1p[kk];
        u64 a1 = a0;
        const u64* __restrict__ wp = &s_w1p[kk * 28];
#pragma unroll
        for (int j = 0; j < 27; j++) {
            int c  = j / 9;
            int kh = (j / 3) % 3;
            int kw = j % 3;
            u64 w = wp[j];
            a0 = fma2(wr2[c][kh][kw],     w, a0);
            a1 = fma2(wr2[c][kh + 1][kw], w, a1);
        }

        const int kh = kk / 3;
        const int kw = kk - 3 * kh;

#pragma unroll
        for (int p = 0; p < 2; p++) {
            float dy, dx;
            unpack2(p ? a1 : a0, dy, dx);
            int ho = hoA + p;
            float py = (float)(ho + kh) + dy;
            float px = (float)(wo + kw) + dx;
            float fy0 = floorf(py);
            float fx0 = floorf(px);
            float wy = py - fy0;
            float wx = px - fx0;
            int y0 = (int)fy0;
            int x0 = (int)fx0;

            bool vy0 = (y0 >= 0)  && (y0 <= IH - 1);
            bool vy1 = (y0 >= -1) && (y0 <= IH - 2);
            bool vx0 = (x0 >= 0)  && (x0 <= IW - 1);
            bool vx1 = (x0 >= -1) && (x0 <= IW - 2);

            float m00 = (1.f - wy) * (1.f - wx) * ((vy0 && vx0) ? 1.f : 0.f);
            float m01 = (1.f - wy) * wx         * ((vy0 && vx1) ? 1.f : 0.f);
            float m10 = wy * (1.f - wx)         * ((vy1 && vx0) ? 1.f : 0.f);
            float m11 = wy * wx                 * ((vy1 && vx1) ? 1.f : 0.f);

            int ly0 = y0 - rowBase;
            int lx0 = x0 - colBase;

            if ((unsigned)ly0 <= TH - 2 && (unsigned)lx0 <= TW - 2) {
                // fast path: all 4 corners inside the shared tile
                int t = ly0 * TW + lx0;
#pragma unroll
                for (int c = 0; c < 3; c++) {
                    const float* __restrict__ tc = &s_tile[c * TILE_CH + t];
                    float v = m00 * tc[0] + m01 * tc[1]
                            + m10 * tc[TW] + m11 * tc[TW + 1];
                    acc[p][0] = fmaf(v, s_w2[0 * 27 + c * 9 + kk], acc[p][0]);
                    acc[p][1] = fmaf(v, s_w2[1 * 27 + c * 9 + kk], acc[p][1]);
                    acc[p][2] = fmaf(v, s_w2[2 * 27 + c * 9 + kk], acc[p][2]);
                }
            } else {
                // rare slow path: clamped global loads (exact reference semantics)
                int yc0 = min(max(y0, 0), IH - 1);
                int yc1 = min(max(y0 + 1, 0), IH - 1);
                int xc0 = min(max(x0, 0), IW - 1);
                int xc1 = min(max(x0 + 1, 0), IW - 1);
                int i00 = yc0 * IW + xc0;
                int i01 = yc0 * IW + xc1;
                int i10 = yc1 * IW + xc0;
                int i11 = yc1 * IW + xc1;
#pragma unroll
                for (int c = 0; c < 3; c++) {
                    const float* __restrict__ xc = xb + (size_t)c * IH * IW;
                    float v = m00 * __ldg(xc + i00) + m01 * __ldg(xc + i01)
                            + m10 * __ldg(xc + i10) + m11 * __ldg(xc + i11);
                    acc[p][0] = fmaf(v, s_w2[0 * 27 + c * 9 + kk], acc[p][0]);
                    acc[p][1] = fmaf(v, s_w2[1 * 27 + c * 9 + kk], acc[p][1]);
                    acc[p][2] = fmaf(v, s_w2[2 * 27 + c * 9 + kk], acc[p][2]);
                }
            }
        }
    }

    // ---- store ----
    if (wo < WO) {
        const size_t plane = (size_t)HO * WO;
#pragma unroll
        for (int p = 0; p < 2; p++) {
            int ho = hoA + p;
            if (ho < HO) {
                size_t ob = (size_t)b * 3 * plane + (size_t)ho * WO + wo;
                out[ob]             = acc[p][0];
                out[ob + plane]     = acc[p][1];
                out[ob + 2 * plane] = acc[p][2];
            }
        }
    }
}

extern "C" void kernel_launch(void* const* d_in, const int* in_sizes, int n_in,
                              void* d_out, int out_size)
{
    const float* x  = (const float*)d_in[0];
    const float* w1 = (const float*)d_in[1];
    const float* b1 = (const float*)d_in[2];
    const float* w2 = (const float*)d_in[3];
    const float* b2 = (const float*)d_in[4];
    float* out = (float*)d_out;

    dim3 block(32, 4, 1);
    dim3 grid((WO + 31) / 32, (HO + 7) / 8, NB);
    deform_fused2<<<grid, block>>>(x, w1, b1, w2, b2, out);
}